// round 6
// baseline (speedup 1.0000x reference)
#include <cuda_runtime.h>
#include <cuda_bf16.h>
#include <math.h>

// ---------------------------------------------------------------------------
// RITS / BRITS-style recurrent imputation. B=512, T=128, D=H=128.
// Launches: prep(+denom), mergedGEMM(Gh,Gx,Gm), betaGEMM, seq  (4 total)
// seq: 64 CTAs x 8 batch rows x 512 threads -> Wg read once per CTA per step.
// ---------------------------------------------------------------------------

#define T_STEPS  128
#define DD       128

typedef unsigned long long ull;

__device__ __align__(16) float g_Gh[8388608];     // [BT, 128]
__device__ __align__(16) float g_Gx[8388608];     // [BT, 128]
__device__ __align__(16) float g_Beta[8388608];   // [BT, 128]
__device__ __align__(16) float g_Gm[33554432];    // [BT, 512]
__device__ __align__(16) float g_den[128];
__device__ __align__(16) float g_WthT[16384];
__device__ __align__(16) float g_WtxT[16384];
__device__ __align__(16) float g_WhrQ[16384];     // [32 k4][128 j][4 e]
__device__ __align__(16) float g_WfrQ[16384];     // [32 k4][128 j][4 e]
__device__ __align__(16) float g_WgQ[131072];     // [64 k4][512 n][4 e]

__device__ __forceinline__ float sigmoidf_(float x) { return 1.0f / (1.0f + expf(-x)); }

__device__ __forceinline__ void ffma2(ull& d, ull a, ull b) {
    asm("fma.rn.f32x2 %0, %1, %2, %0;" : "+l"(d) : "l"(a), "l"(b));
}
__device__ __forceinline__ ull packf2(float a, float b) {
    ull u; asm("mov.b64 %0, {%1, %2};" : "=l"(u) : "f"(a), "f"(b)); return u;
}
__device__ __forceinline__ float hsum2(ull u) {
    float x, y; asm("mov.b64 {%0, %1}, %2;" : "=f"(x), "=f"(y) : "l"(u));
    return x + y;
}
__device__ __forceinline__ float2 unpackf2(ull u) {
    float2 r; asm("mov.b64 {%0, %1}, %2;" : "=f"(r.x), "=f"(r.y) : "l"(u));
    return r;
}

// ---------------------------------------------------------------------------
// Prep: transposes + quad-k repacks + denom (blocks < 128)
// ---------------------------------------------------------------------------
__global__ void prep_weights(const float* __restrict__ Wth, const float* __restrict__ Wtx,
                             const float* __restrict__ Whr, const float* __restrict__ Wfr,
                             const float* __restrict__ Wk,  const float* __restrict__ Wr,
                             const float* __restrict__ masks,
                             float* __restrict__ WthT, float* __restrict__ WtxT,
                             float* __restrict__ WhrQ, float* __restrict__ WfrQ,
                             float* __restrict__ WgQ,  float* __restrict__ den)
{
    int idx = blockIdx.x * blockDim.x + threadIdx.x;
    if (idx < 16384) {
        int k = idx >> 7, j = idx & 127;
        WthT[idx] = Wth[j * 128 + k];
        WtxT[idx] = Wtx[j * 128 + k];
        int k4 = idx >> 9, rem = idx & 511, jj = rem >> 2, e = rem & 3;
        int kk = 4 * k4 + e;
        WhrQ[idx] = Whr[kk * 128 + jj];
        WfrQ[idx] = Wfr[jj * 128 + kk];
    }
    if (idx < 131072) {
        int k4 = idx >> 11, rem = idx & 2047, n = rem >> 2, e = rem & 3;
        int k = 4 * k4 + e;
        WgQ[idx] = (k < 128) ? Wk[k * 512 + n] : Wr[(k - 128) * 512 + n];
    }
    if (blockIdx.x < 128) {
        int t = blockIdx.x;
        float s = 0.0f;
        for (int i = threadIdx.x; i < 512 * 128; i += blockDim.x) {
            int b = i >> 7, d = i & 127;
            s += masks[((size_t)b * T_STEPS + t) * DD + d];
        }
        __shared__ float red[256];
        red[threadIdx.x] = s;
        __syncthreads();
        for (int off = 128; off > 0; off >>= 1) {
            if (threadIdx.x < off) red[threadIdx.x] += red[threadIdx.x + off];
            __syncthreads();
        }
        if (threadIdx.x == 0) den[t] = red[0] + 1e-6f;
    }
}

// ---------------------------------------------------------------------------
// GEMM body: C[bm:bm+64, bn:bn+64] = epi(A @ B + bias), packed f32x2 FMAs.
// ---------------------------------------------------------------------------
__device__ __forceinline__ void gemm_body(
    const float* __restrict__ A1, const float* __restrict__ A2,
    const float* __restrict__ B, const float* __restrict__ bias,
    float* __restrict__ C, int N, int K, int epi, int bm, int bn)
{
    __shared__ float As[64][16];
    __shared__ float Bs[16][64];

    const int tid = threadIdx.x;
    const int tx = tid & 15;
    const int ty = tid >> 4;
    const int arow = tid >> 2;
    const int ak4 = (tid & 3) * 4;
    const int bk = tid >> 4;
    const int bn4 = (tid & 15) * 4;

    ull acc[4][2];
#pragma unroll
    for (int i = 0; i < 4; i++) { acc[i][0] = 0ULL; acc[i][1] = 0ULL; }

    for (int k0 = 0; k0 < K; k0 += 16) {
        const float* Ab;
        int kloc;
        if (k0 < 128) { Ab = A1; kloc = k0; } else { Ab = A2; kloc = k0 - 128; }
        float4 av = *(const float4*)&Ab[(size_t)(bm + arow) * 128 + kloc + ak4];
        *(float4*)&As[arow][ak4] = av;
        float4 bv = *(const float4*)&B[(size_t)(k0 + bk) * N + bn + bn4];
        *(float4*)&Bs[bk][bn4] = bv;
        __syncthreads();
#pragma unroll
        for (int kk = 0; kk < 16; kk++) {
            ull b01 = *(const ull*)&Bs[kk][tx * 4];
            ull b23 = *(const ull*)&Bs[kk][tx * 4 + 2];
#pragma unroll
            for (int i = 0; i < 4; i++) {
                float a = As[ty * 4 + i][kk];
                ull ap = packf2(a, a);
                ffma2(acc[i][0], ap, b01);
                ffma2(acc[i][1], ap, b23);
            }
        }
        __syncthreads();
    }

#pragma unroll
    for (int i = 0; i < 4; i++) {
        float2 c01 = unpackf2(acc[i][0]);
        float2 c23 = unpackf2(acc[i][1]);
        float4 ov;
        ov.x = c01.x + bias[bn + tx * 4 + 0];
        ov.y = c01.y + bias[bn + tx * 4 + 1];
        ov.z = c23.x + bias[bn + tx * 4 + 2];
        ov.w = c23.y + bias[bn + tx * 4 + 3];
        if (epi == 0) {
            ov.x = expf(-fmaxf(ov.x, 0.0f));
            ov.y = expf(-fmaxf(ov.y, 0.0f));
            ov.z = expf(-fmaxf(ov.z, 0.0f));
            ov.w = expf(-fmaxf(ov.w, 0.0f));
        }
        *(float4*)&C[(size_t)(bm + ty * 4 + i) * N + bn + tx * 4] = ov;
    }
}

// Merged GEMM: y 0-1 -> Gh, y 2-3 -> Gx, y 4-11 -> Gm
__global__ void __launch_bounds__(256) gemm_merged(
    const float* __restrict__ deltas, const float* __restrict__ masks,
    const float* __restrict__ WthT, const float* __restrict__ bth,
    const float* __restrict__ WtxT, const float* __restrict__ btx,
    const float* __restrict__ WkBot, const float* __restrict__ bl,
    float* __restrict__ Gh, float* __restrict__ Gx, float* __restrict__ Gm)
{
    int bm = blockIdx.x * 64;
    int y = blockIdx.y;
    if (y < 2)       gemm_body(deltas, nullptr, WthT, bth, Gh, 128, 128, 0, bm, y * 64);
    else if (y < 4)  gemm_body(deltas, nullptr, WtxT, btx, Gx, 128, 128, 0, bm, (y - 2) * 64);
    else             gemm_body(masks,  nullptr, WkBot, bl, Gm, 512, 128, 1, bm, (y - 4) * 64);
}

__global__ void __launch_bounds__(256) gemm_beta(
    const float* __restrict__ Gx, const float* __restrict__ masks,
    const float* __restrict__ Wwc, const float* __restrict__ bwc,
    float* __restrict__ Beta)
{
    gemm_body(Gx, masks, Wwc, bwc, Beta, 128, 256, 1, blockIdx.x * 64, blockIdx.y * 64);
}

// ---------------------------------------------------------------------------
// Sequential recurrence: 64 CTAs x 8 batch rows x 512 threads.
// Thread handles elements (row qa=tid>>7, j=tid&127) and (row qa+4, j).
// Phase E: thread owns gate column n=tid for ALL 8 rows -> Wg read once/CTA.
// E h-half issued right after S1 (overlaps B/C with its L2 loads).
// ---------------------------------------------------------------------------
__global__ void __launch_bounds__(512, 1) seq_kernel(
    const float* __restrict__ values, const float* __restrict__ masks,
    const float* __restrict__ WhrQ_g, const float* __restrict__ bhr,
    const float* __restrict__ bfr,    const float* __restrict__ WfrQ_g,
    const float* __restrict__ Gh,     const float* __restrict__ Beta,
    const float* __restrict__ Gm,     const float* __restrict__ den,
    const float* __restrict__ Wd,     const float* __restrict__ bd,
    const float* __restrict__ Wo,     const float* __restrict__ bo,
    const float* __restrict__ WgQ,
    float* __restrict__ out_pred, float* __restrict__ out_imp,
    float* __restrict__ out_loss)
{
    extern __shared__ float sm[];
    float* sWhrQ = sm;                       // 16384
    float* sWfrQ = sm + 16384;               // 16384
    float* sh    = sm + 32768;               // 1024 (8 rows x 128)
    float* sc    = sh + 1024;                // 1024
    float* sxc   = sc + 1024;                // 1024
    float* scc   = sxc + 1024;               // 1024
    float* sg    = scc + 1024;               // 4096 (8 rows x 512)
    float* sbhr  = sg + 4096;                // 128
    float* sbfr  = sbhr + 128;               // 128

    const int tid = threadIdx.x;
    const int b0 = blockIdx.x * 8;

    for (int i = tid; i < 16384; i += 512) { sWhrQ[i] = WhrQ_g[i]; sWfrQ[i] = WfrQ_g[i]; }
    if (tid < 128) { sbhr[tid] = bhr[tid]; sbfr[tid] = bfr[tid]; }
    for (int i = tid; i < 1024; i += 512) { sh[i] = 0.0f; sc[i] = 0.0f; }
    __syncthreads();

    const int j  = tid & 127;
    const int qa = tid >> 7;                  // rows qa and qa+4
    const int qb = qa + 4;
    const size_t rowa = (size_t)(b0 + qa) * T_STEPS;
    const size_t rowb = (size_t)(b0 + qb) * T_STEPS;

    float lsa = 0.0f, lsb = 0.0f;

    // prefetch t=0
    float cxa = values[rowa * DD + j], cxb = values[rowb * DD + j];
    float cma = masks[rowa * DD + j],  cmb = masks[rowb * DD + j];
    float cga = Gh[rowa * DD + j],     cgb = Gh[rowb * DD + j];
    float cba = Beta[rowa * DD + j],   cbb = Beta[rowb * DD + j];
    float cden = den[0];

    const float* wq = WgQ + (size_t)tid * 4;       // gate column n = tid

    for (int t = 0; t < T_STEPS; t++) {
        const size_t bta = rowa + t, btb = rowb + t;

        // --- Phase A: decay h (2 elements) ---
        float xa = cxa, xb = cxb, ma = cma, mb = cmb;
        float ha = sh[qa * DD + j] * cga;
        float hb = sh[qb * DD + j] * cgb;
        sh[qa * DD + j] = ha;
        sh[qb * DD + j] = hb;
        float rd = 1.0f / cden;
        float bea = cba, beb = cbb;
        __syncthreads();                                   // S1

        // --- prefetch next step ---
        {
            int tn = (t + 1 < T_STEPS) ? (t + 1) : (T_STEPS - 1);
            size_t na = rowa + tn, nb = rowb + tn;
            cxa = values[na * DD + j]; cxb = values[nb * DD + j];
            cma = masks[na * DD + j];  cmb = masks[nb * DD + j];
            cga = Gh[na * DD + j];     cgb = Gh[nb * DD + j];
            cba = Beta[na * DD + j];   cbb = Beta[nb * DD + j];
            cden = den[tn];
        }

        // --- Gm init for 8 rows (col n = tid) ---
        ull acc[8];
#pragma unroll
        for (int r = 0; r < 8; r++)
            acc[r] = packf2(Gm[((size_t)(b0 + r) * T_STEPS + t) * 512 + tid], 0.0f);

        // --- Phase E (h-half): gates += h @ Wg[128:256], k4 32..63 streamed ---
#pragma unroll 4
        for (int k4 = 32; k4 < 64; k4++) {
            ulonglong2 w = *(const ulonglong2*)&wq[(size_t)k4 * 2048];
            int ko = (k4 - 32) * 4;
#pragma unroll
            for (int r = 0; r < 8; r++) {
                ulonglong2 v = *(const ulonglong2*)&sh[r * DD + ko];
                ffma2(acc[r], v.x, w.x);
                ffma2(acc[r], v.y, w.y);
            }
        }

        // --- Phase B: x_hat = h @ Whr + bhr (2 elements, 2 chains) ---
        ull aa = packf2(sbhr[j], 0.0f), ab = aa;
#pragma unroll 8
        for (int k4 = 0; k4 < 32; k4++) {
            ulonglong2 w = *(const ulonglong2*)&sWhrQ[k4 * 512 + j * 4];
            ulonglong2 va = *(const ulonglong2*)&sh[qa * DD + k4 * 4];
            ulonglong2 vb = *(const ulonglong2*)&sh[qb * DD + k4 * 4];
            ffma2(aa, va.x, w.x); ffma2(aa, va.y, w.y);
            ffma2(ab, vb.x, w.x); ffma2(ab, vb.y, w.y);
        }
        float xha = hsum2(aa), xhb = hsum2(ab);
        float xca = ma * xa + (1.0f - ma) * xha;
        float xcb = mb * xb + (1.0f - mb) * xhb;
        sxc[qa * DD + j] = xca;
        sxc[qb * DD + j] = xcb;
        lsa += fabsf(xa - xha) * ma * rd;
        lsb += fabsf(xb - xhb) * mb * rd;
        __syncthreads();                                   // S2

        // --- Phase C: z_hat = x_c @ Wfr^T + bfr ---
        aa = packf2(sbfr[j], 0.0f); ab = aa;
#pragma unroll 8
        for (int k4 = 0; k4 < 32; k4++) {
            ulonglong2 w = *(const ulonglong2*)&sWfrQ[k4 * 512 + j * 4];
            ulonglong2 va = *(const ulonglong2*)&sxc[qa * DD + k4 * 4];
            ulonglong2 vb = *(const ulonglong2*)&sxc[qb * DD + k4 * 4];
            ffma2(aa, va.x, w.x); ffma2(aa, va.y, w.y);
            ffma2(ab, vb.x, w.x); ffma2(ab, vb.y, w.y);
        }
        float zha = hsum2(aa), zhb = hsum2(ab);
        lsa += fabsf(xa - zha) * ma * rd;
        lsb += fabsf(xb - zhb) * mb * rd;

        // --- Phase D: c_hat / c_c / imputation ---
        float cha = bea * zha + (1.0f - bea) * xha;
        float chb = beb * zhb + (1.0f - beb) * xhb;
        lsa += fabsf(xa - cha) * ma * rd;
        lsb += fabsf(xb - chb) * mb * rd;
        float cca = ma * xa + (1.0f - ma) * cha;
        float ccb = mb * xb + (1.0f - mb) * chb;
        scc[qa * DD + j] = cca;
        scc[qb * DD + j] = ccb;
        out_imp[bta * DD + j] = cca;
        out_imp[btb * DD + j] = ccb;
        __syncthreads();                                   // S3

        // --- Phase E (cc-half): gates += cc @ Wg[0:128], k4 0..31 streamed ---
#pragma unroll 4
        for (int k4 = 0; k4 < 32; k4++) {
            ulonglong2 w = *(const ulonglong2*)&wq[(size_t)k4 * 2048];
            int ko = k4 * 4;
#pragma unroll
            for (int r = 0; r < 8; r++) {
                ulonglong2 v = *(const ulonglong2*)&scc[r * DD + ko];
                ffma2(acc[r], v.x, w.x);
                ffma2(acc[r], v.y, w.y);
            }
        }
#pragma unroll
        for (int r = 0; r < 8; r++)
            sg[r * 512 + tid] = hsum2(acc[r]);
        __syncthreads();                                   // S4

        // --- Phase F: LSTM cell update (i, f, g, o), 2 elements ---
        {
            float gi = sg[qa * 512 + j];
            float gf = sg[qa * 512 + 128 + j];
            float gg = sg[qa * 512 + 256 + j];
            float go = sg[qa * 512 + 384 + j];
            float cn = sigmoidf_(gf) * sc[qa * DD + j] + sigmoidf_(gi) * tanhf(gg);
            sc[qa * DD + j] = cn;
            sh[qa * DD + j] = sigmoidf_(go) * tanhf(cn);
        }
        {
            float gi = sg[qb * 512 + j];
            float gf = sg[qb * 512 + 128 + j];
            float gg = sg[qb * 512 + 256 + j];
            float go = sg[qb * 512 + 384 + j];
            float cn = sigmoidf_(gf) * sc[qb * DD + j] + sigmoidf_(gi) * tanhf(gg);
            sc[qb * DD + j] = cn;
            sh[qb * DD + j] = sigmoidf_(go) * tanhf(cn);
        }
    }

    __syncthreads();

    // --- custom_loss (8 rows) ---
    sg[qa * DD + j] = lsa;
    sg[qb * DD + j] = lsb;
    __syncthreads();
    if (tid < 8) {
        float s = 0.0f;
        for (int k = 0; k < 128; k++) s += sg[tid * DD + k];
        out_loss[b0 + tid] = s * (1.0f / T_STEPS);
    }
    __syncthreads();

    // --- predictions = relu(h @ Wd + bd) @ Wo + bo ---
    float pa = bd[j], pb = bd[j];
    for (int k = 0; k < 128; k++) {
        float w = Wd[k * DD + j];
        pa = fmaf(sh[qa * DD + k], w, pa);
        pb = fmaf(sh[qb * DD + k], w, pb);
    }
    float wo = Wo[j];
    sg[qa * DD + j] = fmaxf(pa, 0.0f) * wo;
    sg[qb * DD + j] = fmaxf(pb, 0.0f) * wo;
    __syncthreads();
    if (tid < 8) {
        float s = 0.0f;
        for (int k = 0; k < 128; k++) s += sg[tid * DD + k];
        out_pred[b0 + tid] = s + bo[0];
    }
}

// ---------------------------------------------------------------------------
extern "C" void kernel_launch(void* const* d_in, const int* in_sizes, int n_in,
                              void* d_out, int out_size)
{
    const float* values = (const float*)d_in[0];
    const float* masks  = (const float*)d_in[1];
    const float* deltas = (const float*)d_in[2];
    const float* Wth    = (const float*)d_in[3];
    const float* bth    = (const float*)d_in[4];
    const float* Wtx    = (const float*)d_in[5];
    const float* btx    = (const float*)d_in[6];
    const float* Whr    = (const float*)d_in[7];
    const float* bhr    = (const float*)d_in[8];
    const float* Wfr    = (const float*)d_in[9];
    const float* bfr    = (const float*)d_in[10];
    const float* Wwc    = (const float*)d_in[11];
    const float* bwc    = (const float*)d_in[12];
    const float* Wk     = (const float*)d_in[13];
    const float* Wr     = (const float*)d_in[14];
    const float* bl     = (const float*)d_in[15];
    const float* Wd     = (const float*)d_in[16];
    const float* bd     = (const float*)d_in[17];
    const float* Wo     = (const float*)d_in[18];
    const float* bo     = (const float*)d_in[19];

    float *pGh, *pGx, *pBeta, *pGm, *pDen, *pWthT, *pWtxT, *pWhrQ, *pWfrQ, *pWgQ;
    cudaGetSymbolAddress((void**)&pGh,   g_Gh);
    cudaGetSymbolAddress((void**)&pGx,   g_Gx);
    cudaGetSymbolAddress((void**)&pBeta, g_Beta);
    cudaGetSymbolAddress((void**)&pGm,   g_Gm);
    cudaGetSymbolAddress((void**)&pDen,  g_den);
    cudaGetSymbolAddress((void**)&pWthT, g_WthT);
    cudaGetSymbolAddress((void**)&pWtxT, g_WtxT);
    cudaGetSymbolAddress((void**)&pWhrQ, g_WhrQ);
    cudaGetSymbolAddress((void**)&pWfrQ, g_WfrQ);
    cudaGetSymbolAddress((void**)&pWgQ,  g_WgQ);

    // Launch 0: prep (incl. denom)
    prep_weights<<<512, 256>>>(Wth, Wtx, Whr, Wfr, Wk, Wr, masks,
                               pWthT, pWtxT, pWhrQ, pWfrQ, pWgQ, pDen);

    // Launch 1: merged GEMM (Gh, Gx, Gm)
    dim3 gm(1024, 12);
    gemm_merged<<<gm, 256>>>(deltas, masks, pWthT, bth, pWtxT, btx,
                             Wk + 128 * 512, bl, pGh, pGx, pGm);

    // Launch 2: Beta (consumes Gx)
    dim3 gb(1024, 2);
    gemm_beta<<<gb, 256>>>(pGx, masks, Wwc, bwc, pBeta);

    // Launch 3: sequential recurrence (64 CTAs x 8 rows)
    float* out = (float*)d_out;
    const size_t SMEM = (size_t)(16384 * 2 + 1024 * 4 + 4096 + 256) * sizeof(float); // 165,888 B
    cudaFuncSetAttribute(seq_kernel, cudaFuncAttributeMaxDynamicSharedMemorySize, (int)SMEM);
    seq_kernel<<<64, 512, SMEM>>>(values, masks, pWhrQ, bhr, bfr, pWfrQ,
                                  pGh, pBeta, pGm, pDen,
                                  Wd, bd, Wo, bo, pWgQ,
                                  out,                     // predictions [512]
                                  out + 512,               // imputations [512*128*128]
                                  out + 512 + 8388608);    // custom_loss [512]
}

// round 7
// speedup vs baseline: 1.4191x; 1.4191x over previous
#include <cuda_runtime.h>
#include <cuda_bf16.h>
#include <math.h>

// ---------------------------------------------------------------------------
// RITS / BRITS-style recurrent imputation. B=512, T=128, D=H=128.
// Launches: prep(+denom), mergedGEMM(Gh,Gx,Gm), betaGEMM, seq  (4 total)
// seq = R4 champion config: 128 CTAs x 4 rows x 512 threads.
// ---------------------------------------------------------------------------

#define T_STEPS  128
#define DD       128

typedef unsigned long long ull;

__device__ __align__(16) float g_Gh[8388608];     // [BT, 128]
__device__ __align__(16) float g_Gx[8388608];     // [BT, 128]
__device__ __align__(16) float g_Beta[8388608];   // [BT, 128]
__device__ __align__(16) float g_Gm[33554432];    // [BT, 512]
__device__ __align__(16) float g_den[128];
__device__ __align__(16) float g_WthT[16384];
__device__ __align__(16) float g_WtxT[16384];
__device__ __align__(16) float g_WhrQ[16384];     // [32 k4][128 j][4 e]
__device__ __align__(16) float g_WfrQ[16384];     // [32 k4][128 j][4 e]
__device__ __align__(16) float g_WgQ[131072];     // [64 k4][512 n][4 e]

__device__ __forceinline__ float sigmoidf_(float x) { return 1.0f / (1.0f + expf(-x)); }

__device__ __forceinline__ void ffma2(ull& d, ull a, ull b) {
    asm("fma.rn.f32x2 %0, %1, %2, %0;" : "+l"(d) : "l"(a), "l"(b));
}
__device__ __forceinline__ ull packf2(float a, float b) {
    ull u; asm("mov.b64 %0, {%1, %2};" : "=l"(u) : "f"(a), "f"(b)); return u;
}
__device__ __forceinline__ float hsum2(ull u) {
    float x, y; asm("mov.b64 {%0, %1}, %2;" : "=f"(x), "=f"(y) : "l"(u));
    return x + y;
}
__device__ __forceinline__ float2 unpackf2(ull u) {
    float2 r; asm("mov.b64 {%0, %1}, %2;" : "=f"(r.x), "=f"(r.y) : "l"(u));
    return r;
}

// ---------------------------------------------------------------------------
// Prep: transposes + quad-k repacks + denom (blocks < 128)
// ---------------------------------------------------------------------------
__global__ void prep_weights(const float* __restrict__ Wth, const float* __restrict__ Wtx,
                             const float* __restrict__ Whr, const float* __restrict__ Wfr,
                             const float* __restrict__ Wk,  const float* __restrict__ Wr,
                             const float* __restrict__ masks,
                             float* __restrict__ WthT, float* __restrict__ WtxT,
                             float* __restrict__ WhrQ, float* __restrict__ WfrQ,
                             float* __restrict__ WgQ,  float* __restrict__ den)
{
    int idx = blockIdx.x * blockDim.x + threadIdx.x;
    if (idx < 16384) {
        int k = idx >> 7, j = idx & 127;
        WthT[idx] = Wth[j * 128 + k];
        WtxT[idx] = Wtx[j * 128 + k];
        int k4 = idx >> 9, rem = idx & 511, jj = rem >> 2, e = rem & 3;
        int kk = 4 * k4 + e;
        WhrQ[idx] = Whr[kk * 128 + jj];
        WfrQ[idx] = Wfr[jj * 128 + kk];
    }
    if (idx < 131072) {
        int k4 = idx >> 11, rem = idx & 2047, n = rem >> 2, e = rem & 3;
        int k = 4 * k4 + e;
        WgQ[idx] = (k < 128) ? Wk[k * 512 + n] : Wr[(k - 128) * 512 + n];
    }
    if (blockIdx.x < 128) {
        int t = blockIdx.x;
        float s = 0.0f;
        for (int i = threadIdx.x; i < 512 * 128; i += blockDim.x) {
            int b = i >> 7, d = i & 127;
            s += masks[((size_t)b * T_STEPS + t) * DD + d];
        }
        __shared__ float red[256];
        red[threadIdx.x] = s;
        __syncthreads();
        for (int off = 128; off > 0; off >>= 1) {
            if (threadIdx.x < off) red[threadIdx.x] += red[threadIdx.x + off];
            __syncthreads();
        }
        if (threadIdx.x == 0) den[t] = red[0] + 1e-6f;
    }
}

// ---------------------------------------------------------------------------
// GEMM body: C[bm:bm+64, bn:bn+64] = epi(A @ B + bias), packed f32x2 FMAs.
// A split column-wise at k=128 (A1/A2, both lda=128). BK=16, 256 threads.
// ---------------------------------------------------------------------------
__device__ __forceinline__ void gemm_body(
    const float* __restrict__ A1, const float* __restrict__ A2,
    const float* __restrict__ B, const float* __restrict__ bias,
    float* __restrict__ C, int N, int K, int epi, int bm, int bn)
{
    __shared__ float As[64][16];
    __shared__ float Bs[16][64];

    const int tid = threadIdx.x;
    const int tx = tid & 15;
    const int ty = tid >> 4;
    const int arow = tid >> 2;
    const int ak4 = (tid & 3) * 4;
    const int bk = tid >> 4;
    const int bn4 = (tid & 15) * 4;

    ull acc[4][2];
#pragma unroll
    for (int i = 0; i < 4; i++) { acc[i][0] = 0ULL; acc[i][1] = 0ULL; }

    for (int k0 = 0; k0 < K; k0 += 16) {
        const float* Ab;
        int kloc;
        if (k0 < 128) { Ab = A1; kloc = k0; } else { Ab = A2; kloc = k0 - 128; }
        float4 av = *(const float4*)&Ab[(size_t)(bm + arow) * 128 + kloc + ak4];
        *(float4*)&As[arow][ak4] = av;
        float4 bv = *(const float4*)&B[(size_t)(k0 + bk) * N + bn + bn4];
        *(float4*)&Bs[bk][bn4] = bv;
        __syncthreads();
#pragma unroll
        for (int kk = 0; kk < 16; kk++) {
            ull b01 = *(const ull*)&Bs[kk][tx * 4];
            ull b23 = *(const ull*)&Bs[kk][tx * 4 + 2];
#pragma unroll
            for (int i = 0; i < 4; i++) {
                float a = As[ty * 4 + i][kk];
                ull ap = packf2(a, a);
                ffma2(acc[i][0], ap, b01);
                ffma2(acc[i][1], ap, b23);
            }
        }
        __syncthreads();
    }

#pragma unroll
    for (int i = 0; i < 4; i++) {
        float2 c01 = unpackf2(acc[i][0]);
        float2 c23 = unpackf2(acc[i][1]);
        float4 ov;
        ov.x = c01.x + bias[bn + tx * 4 + 0];
        ov.y = c01.y + bias[bn + tx * 4 + 1];
        ov.z = c23.x + bias[bn + tx * 4 + 2];
        ov.w = c23.y + bias[bn + tx * 4 + 3];
        if (epi == 0) {
            ov.x = expf(-fmaxf(ov.x, 0.0f));
            ov.y = expf(-fmaxf(ov.y, 0.0f));
            ov.z = expf(-fmaxf(ov.z, 0.0f));
            ov.w = expf(-fmaxf(ov.w, 0.0f));
        }
        *(float4*)&C[(size_t)(bm + ty * 4 + i) * N + bn + tx * 4] = ov;
    }
}

// Merged GEMM: y 0-1 -> Gh, y 2-3 -> Gx, y 4-11 -> Gm
__global__ void __launch_bounds__(256) gemm_merged(
    const float* __restrict__ deltas, const float* __restrict__ masks,
    const float* __restrict__ WthT, const float* __restrict__ bth,
    const float* __restrict__ WtxT, const float* __restrict__ btx,
    const float* __restrict__ WkBot, const float* __restrict__ bl,
    float* __restrict__ Gh, float* __restrict__ Gx, float* __restrict__ Gm)
{
    int bm = blockIdx.x * 64;
    int y = blockIdx.y;
    if (y < 2)       gemm_body(deltas, nullptr, WthT, bth, Gh, 128, 128, 0, bm, y * 64);
    else if (y < 4)  gemm_body(deltas, nullptr, WtxT, btx, Gx, 128, 128, 0, bm, (y - 2) * 64);
    else             gemm_body(masks,  nullptr, WkBot, bl, Gm, 512, 128, 1, bm, (y - 4) * 64);
}

__global__ void __launch_bounds__(256) gemm_beta(
    const float* __restrict__ Gx, const float* __restrict__ masks,
    const float* __restrict__ Wwc, const float* __restrict__ bwc,
    float* __restrict__ Beta)
{
    gemm_body(Gx, masks, Wwc, bwc, Beta, 128, 256, 1, blockIdx.x * 64, blockIdx.y * 64);
}

// ---------------------------------------------------------------------------
// Sequential recurrence (R4 champion): 128 CTAs x 4 rows x 512 threads.
// Quad-k packed FFMA2, whole Phase E after S3 (full-MLP 64x LDG.128 burst).
// ---------------------------------------------------------------------------
__global__ void __launch_bounds__(512, 1) seq_kernel(
    const float* __restrict__ values, const float* __restrict__ masks,
    const float* __restrict__ WhrQ_g, const float* __restrict__ bhr,
    const float* __restrict__ bfr,    const float* __restrict__ WfrQ_g,
    const float* __restrict__ Gh,     const float* __restrict__ Beta,
    const float* __restrict__ Gm,     const float* __restrict__ den,
    const float* __restrict__ Wd,     const float* __restrict__ bd,
    const float* __restrict__ Wo,     const float* __restrict__ bo,
    const float* __restrict__ WgQ,
    float* __restrict__ out_pred, float* __restrict__ out_imp,
    float* __restrict__ out_loss)
{
    extern __shared__ float sm[];
    float* sWhrQ = sm;                 // 16384
    float* sWfrQ = sm + 16384;         // 16384
    float* sh    = sm + 32768;         // 512
    float* sc    = sh + 512;           // 512
    float* sxc   = sc + 512;           // 512
    float* scc   = sxc + 512;          // 512
    float* sg    = scc + 512;          // 2048
    float* sbhr  = sg + 2048;          // 128
    float* sbfr  = sbhr + 128;         // 128

    const int tid = threadIdx.x;
    const int b0 = blockIdx.x * 4;

    for (int i = tid; i < 16384; i += 512) { sWhrQ[i] = WhrQ_g[i]; sWfrQ[i] = WfrQ_g[i]; }
    if (tid < 128) { sbhr[tid] = bhr[tid]; sbfr[tid] = bfr[tid]; }
    if (tid < 512) { sh[tid] = 0.0f; sc[tid] = 0.0f; }
    __syncthreads();

    const int j = tid & 127;
    const int q = tid >> 7;                       // 0..3
    const size_t rowbase = (size_t)(b0 + q) * T_STEPS;

    float lsum = 0.0f;

    float cx = values[rowbase * DD + j];
    float cm = masks[rowbase * DD + j];
    float cg = Gh[rowbase * DD + j];
    float cb = Beta[rowbase * DD + j];
    float cden = den[0];

    const float* wq = WgQ + (size_t)tid * 4;

    for (int t = 0; t < T_STEPS; t++) {
        const size_t bt = rowbase + t;

        // --- Phase A: decay h ---
        float x = cx, m = cm;
        float h = sh[q * DD + j] * cg;
        sh[q * DD + j] = h;
        float rd = 1.0f / cden;
        float be = cb;
        __syncthreads();                                   // S1

        // --- Prefetch next step + Gm(t) for Phase E ---
        {
            int tn = (t + 1 < T_STEPS) ? (t + 1) : (T_STEPS - 1);
            size_t nb = rowbase + tn;
            cx = values[nb * DD + j];
            cm = masks[nb * DD + j];
            cg = Gh[nb * DD + j];
            cb = Beta[nb * DD + j];
            cden = den[tn];
        }
        float gm[4];
#pragma unroll
        for (int r = 0; r < 4; r++)
            gm[r] = Gm[((size_t)(b0 + r) * T_STEPS + t) * 512 + tid];

        // --- Phase B: x_hat = h @ Whr + bhr ---
        ull a = packf2(sbhr[j], 0.0f);
#pragma unroll 8
        for (int k4 = 0; k4 < 32; k4++) {
            ulonglong2 w = *(const ulonglong2*)&sWhrQ[k4 * 512 + j * 4];
            ulonglong2 v = *(const ulonglong2*)&sh[q * DD + k4 * 4];
            ffma2(a, v.x, w.x);
            ffma2(a, v.y, w.y);
        }
        float xh = hsum2(a);
        float xc = m * x + (1.0f - m) * xh;
        sxc[q * DD + j] = xc;
        lsum += fabsf(x - xh) * m * rd;
        __syncthreads();                                   // S2

        // --- Phase C: z_hat = x_c @ Wfr^T + bfr ---
        a = packf2(sbfr[j], 0.0f);
#pragma unroll 8
        for (int k4 = 0; k4 < 32; k4++) {
            ulonglong2 w = *(const ulonglong2*)&sWfrQ[k4 * 512 + j * 4];
            ulonglong2 v = *(const ulonglong2*)&sxc[q * DD + k4 * 4];
            ffma2(a, v.x, w.x);
            ffma2(a, v.y, w.y);
        }
        float zh = hsum2(a);
        lsum += fabsf(x - zh) * m * rd;

        // --- Phase D: c_hat / c_c / imputation ---
        float ch = be * zh + (1.0f - be) * xh;
        lsum += fabsf(x - ch) * m * rd;
        float cc = m * x + (1.0f - m) * ch;
        scc[q * DD + j] = cc;
        out_imp[bt * DD + j] = cc;
        __syncthreads();                                   // S3

        // --- Phase E: gates[n=tid] = Gm + cc @ Wg[0:128] + h @ Wg[128:256] ---
        ull acc0 = packf2(gm[0], 0.0f);
        ull acc1 = packf2(gm[1], 0.0f);
        ull acc2 = packf2(gm[2], 0.0f);
        ull acc3 = packf2(gm[3], 0.0f);
#pragma unroll 4
        for (int k4 = 0; k4 < 32; k4++) {
            ulonglong2 w = *(const ulonglong2*)&wq[(size_t)k4 * 2048];
            ulonglong2 v0 = *(const ulonglong2*)&scc[0 * DD + k4 * 4];
            ulonglong2 v1 = *(const ulonglong2*)&scc[1 * DD + k4 * 4];
            ulonglong2 v2 = *(const ulonglong2*)&scc[2 * DD + k4 * 4];
            ulonglong2 v3 = *(const ulonglong2*)&scc[3 * DD + k4 * 4];
            ffma2(acc0, v0.x, w.x); ffma2(acc0, v0.y, w.y);
            ffma2(acc1, v1.x, w.x); ffma2(acc1, v1.y, w.y);
            ffma2(acc2, v2.x, w.x); ffma2(acc2, v2.y, w.y);
            ffma2(acc3, v3.x, w.x); ffma2(acc3, v3.y, w.y);
        }
#pragma unroll 4
        for (int k4 = 32; k4 < 64; k4++) {
            ulonglong2 w = *(const ulonglong2*)&wq[(size_t)k4 * 2048];
            int ko = (k4 - 32) * 4;
            ulonglong2 v0 = *(const ulonglong2*)&sh[0 * DD + ko];
            ulonglong2 v1 = *(const ulonglong2*)&sh[1 * DD + ko];
            ulonglong2 v2 = *(const ulonglong2*)&sh[2 * DD + ko];
            ulonglong2 v3 = *(const ulonglong2*)&sh[3 * DD + ko];
            ffma2(acc0, v0.x, w.x); ffma2(acc0, v0.y, w.y);
            ffma2(acc1, v1.x, w.x); ffma2(acc1, v1.y, w.y);
            ffma2(acc2, v2.x, w.x); ffma2(acc2, v2.y, w.y);
            ffma2(acc3, v3.x, w.x); ffma2(acc3, v3.y, w.y);
        }
        sg[0 * 512 + tid] = hsum2(acc0);
        sg[1 * 512 + tid] = hsum2(acc1);
        sg[2 * 512 + tid] = hsum2(acc2);
        sg[3 * 512 + tid] = hsum2(acc3);
        __syncthreads();                                   // S4

        // --- Phase F: LSTM cell update (i, f, g, o), element (q, j) ---
        {
            float gi = sg[q * 512 + j];
            float gf = sg[q * 512 + 128 + j];
            float gg = sg[q * 512 + 256 + j];
            float go = sg[q * 512 + 384 + j];
            float cn = sigmoidf_(gf) * sc[q * DD + j] + sigmoidf_(gi) * tanhf(gg);
            sc[q * DD + j] = cn;
            sh[q * DD + j] = sigmoidf_(go) * tanhf(cn);
        }
    }

    __syncthreads();

    // --- custom_loss ---
    sg[q * DD + j] = lsum;
    __syncthreads();
    if (tid < 4) {
        float s = 0.0f;
        for (int k = 0; k < 128; k++) s += sg[tid * DD + k];
        out_loss[b0 + tid] = s * (1.0f / T_STEPS);
    }
    __syncthreads();

    // --- predictions = relu(h @ Wd + bd) @ Wo + bo ---
    float pa = bd[j];
    for (int k = 0; k < 128; k++) {
        pa = fmaf(sh[q * DD + k], Wd[k * DD + j], pa);
    }
    sg[q * DD + j] = fmaxf(pa, 0.0f) * Wo[j];
    __syncthreads();
    if (tid < 4) {
        float s = 0.0f;
        for (int k = 0; k < 128; k++) s += sg[tid * DD + k];
        out_pred[b0 + tid] = s + bo[0];
    }
}

// ---------------------------------------------------------------------------
extern "C" void kernel_launch(void* const* d_in, const int* in_sizes, int n_in,
                              void* d_out, int out_size)
{
    const float* values = (const float*)d_in[0];
    const float* masks  = (const float*)d_in[1];
    const float* deltas = (const float*)d_in[2];
    const float* Wth    = (const float*)d_in[3];
    const float* bth    = (const float*)d_in[4];
    const float* Wtx    = (const float*)d_in[5];
    const float* btx    = (const float*)d_in[6];
    const float* Whr    = (const float*)d_in[7];
    const float* bhr    = (const float*)d_in[8];
    const float* Wfr    = (const float*)d_in[9];
    const float* bfr    = (const float*)d_in[10];
    const float* Wwc    = (const float*)d_in[11];
    const float* bwc    = (const float*)d_in[12];
    const float* Wk     = (const float*)d_in[13];
    const float* Wr     = (const float*)d_in[14];
    const float* bl     = (const float*)d_in[15];
    const float* Wd     = (const float*)d_in[16];
    const float* bd     = (const float*)d_in[17];
    const float* Wo     = (const float*)d_in[18];
    const float* bo     = (const float*)d_in[19];

    float *pGh, *pGx, *pBeta, *pGm, *pDen, *pWthT, *pWtxT, *pWhrQ, *pWfrQ, *pWgQ;
    cudaGetSymbolAddress((void**)&pGh,   g_Gh);
    cudaGetSymbolAddress((void**)&pGx,   g_Gx);
    cudaGetSymbolAddress((void**)&pBeta, g_Beta);
    cudaGetSymbolAddress((void**)&pGm,   g_Gm);
    cudaGetSymbolAddress((void**)&pDen,  g_den);
    cudaGetSymbolAddress((void**)&pWthT, g_WthT);
    cudaGetSymbolAddress((void**)&pWtxT, g_WtxT);
    cudaGetSymbolAddress((void**)&pWhrQ, g_WhrQ);
    cudaGetSymbolAddress((void**)&pWfrQ, g_WfrQ);
    cudaGetSymbolAddress((void**)&pWgQ,  g_WgQ);

    // Launch 0: prep (incl. denom)
    prep_weights<<<512, 256>>>(Wth, Wtx, Whr, Wfr, Wk, Wr, masks,
                               pWthT, pWtxT, pWhrQ, pWfrQ, pWgQ, pDen);

    // Launch 1: merged GEMM (Gh, Gx, Gm) — f32x2 FMAs
    dim3 gm(1024, 12);
    gemm_merged<<<gm, 256>>>(deltas, masks, pWthT, bth, pWtxT, btx,
                             Wk + 128 * 512, bl, pGh, pGx, pGm);

    // Launch 2: Beta (consumes Gx)
    dim3 gb(1024, 2);
    gemm_beta<<<gb, 256>>>(pGx, masks, Wwc, bwc, pBeta);

    // Launch 3: sequential recurrence (R4 config)
    float* out = (float*)d_out;
    const size_t SMEM = (size_t)(16384 * 2 + 512 * 4 + 2048 + 256) * sizeof(float);
    cudaFuncSetAttribute(seq_kernel, cudaFuncAttributeMaxDynamicSharedMemorySize, (int)SMEM);
    seq_kernel<<<128, 512, SMEM>>>(values, masks, pWhrQ, bhr, bfr, pWfrQ,
                                   pGh, pBeta, pGm, pDen,
                                   Wd, bd, Wo, bo, pWgQ,
                                   out,                     // predictions [512]
                                   out + 512,               // imputations [512*128*128]
                                   out + 512 + 8388608);    // custom_loss [512]
}

// round 8
// speedup vs baseline: 1.7964x; 1.2659x over previous
#include <cuda_runtime.h>
#include <cuda_bf16.h>
#include <math.h>

// ---------------------------------------------------------------------------
// RITS / BRITS-style recurrent imputation. B=512, T=128, D=H=128.
// Launches: prep(+denom), mergedGEMM(Gh,Gx,Gm), betaGEMM, seq  (4 total)
// seq: 128 CTAs x 4 rows x 512 threads, k-split partials to minimize L1tex
// wavefronts (the measured bottleneck: L1=76%).
// ---------------------------------------------------------------------------

#define T_STEPS  128
#define DD       128

typedef unsigned long long ull;

__device__ __align__(16) float g_Gh[8388608];     // [BT, 128]
__device__ __align__(16) float g_Gx[8388608];     // [BT, 128]
__device__ __align__(16) float g_Beta[8388608];   // [BT, 128]
__device__ __align__(16) float g_Gm[33554432];    // [BT, 512]
__device__ __align__(16) float g_den[128];
__device__ __align__(16) float g_WthT[16384];
__device__ __align__(16) float g_WtxT[16384];
__device__ __align__(16) float g_WhrQ[16384];     // [32 k4][128 j][4 e]
__device__ __align__(16) float g_WfrQ[16384];     // [32 k4][128 j][4 e]
__device__ __align__(16) float g_WgQ[131072];     // [64 k4][512 n][4 e]

__device__ __forceinline__ float sigmoidf_(float x) { return 1.0f / (1.0f + expf(-x)); }

__device__ __forceinline__ void ffma2(ull& d, ull a, ull b) {
    asm("fma.rn.f32x2 %0, %1, %2, %0;" : "+l"(d) : "l"(a), "l"(b));
}
__device__ __forceinline__ ull packf2(float a, float b) {
    ull u; asm("mov.b64 %0, {%1, %2};" : "=l"(u) : "f"(a), "f"(b)); return u;
}
__device__ __forceinline__ float hsum2(ull u) {
    float x, y; asm("mov.b64 {%0, %1}, %2;" : "=f"(x), "=f"(y) : "l"(u));
    return x + y;
}
__device__ __forceinline__ float2 unpackf2(ull u) {
    float2 r; asm("mov.b64 {%0, %1}, %2;" : "=f"(r.x), "=f"(r.y) : "l"(u));
    return r;
}

// ---------------------------------------------------------------------------
// Prep: transposes + quad-k repacks + denom (blocks < 128)
// ---------------------------------------------------------------------------
__global__ void prep_weights(const float* __restrict__ Wth, const float* __restrict__ Wtx,
                             const float* __restrict__ Whr, const float* __restrict__ Wfr,
                             const float* __restrict__ Wk,  const float* __restrict__ Wr,
                             const float* __restrict__ masks,
                             float* __restrict__ WthT, float* __restrict__ WtxT,
                             float* __restrict__ WhrQ, float* __restrict__ WfrQ,
                             float* __restrict__ WgQ,  float* __restrict__ den)
{
    int idx = blockIdx.x * blockDim.x + threadIdx.x;
    if (idx < 16384) {
        int k = idx >> 7, j = idx & 127;
        WthT[idx] = Wth[j * 128 + k];
        WtxT[idx] = Wtx[j * 128 + k];
        int k4 = idx >> 9, rem = idx & 511, jj = rem >> 2, e = rem & 3;
        int kk = 4 * k4 + e;
        WhrQ[idx] = Whr[kk * 128 + jj];
        WfrQ[idx] = Wfr[jj * 128 + kk];
    }
    if (idx < 131072) {
        int k4 = idx >> 11, rem = idx & 2047, n = rem >> 2, e = rem & 3;
        int k = 4 * k4 + e;
        WgQ[idx] = (k < 128) ? Wk[k * 512 + n] : Wr[(k - 128) * 512 + n];
    }
    if (blockIdx.x < 128) {
        int t = blockIdx.x;
        float s = 0.0f;
        for (int i = threadIdx.x; i < 512 * 128; i += blockDim.x) {
            int b = i >> 7, d = i & 127;
            s += masks[((size_t)b * T_STEPS + t) * DD + d];
        }
        __shared__ float red[256];
        red[threadIdx.x] = s;
        __syncthreads();
        for (int off = 128; off > 0; off >>= 1) {
            if (threadIdx.x < off) red[threadIdx.x] += red[threadIdx.x + off];
            __syncthreads();
        }
        if (threadIdx.x == 0) den[t] = red[0] + 1e-6f;
    }
}

// ---------------------------------------------------------------------------
// GEMM body (precompute), packed f32x2 FMAs. Unchanged from R7.
// ---------------------------------------------------------------------------
__device__ __forceinline__ void gemm_body(
    const float* __restrict__ A1, const float* __restrict__ A2,
    const float* __restrict__ B, const float* __restrict__ bias,
    float* __restrict__ C, int N, int K, int epi, int bm, int bn)
{
    __shared__ float As[64][16];
    __shared__ float Bs[16][64];

    const int tid = threadIdx.x;
    const int tx = tid & 15;
    const int ty = tid >> 4;
    const int arow = tid >> 2;
    const int ak4 = (tid & 3) * 4;
    const int bk = tid >> 4;
    const int bn4 = (tid & 15) * 4;

    ull acc[4][2];
#pragma unroll
    for (int i = 0; i < 4; i++) { acc[i][0] = 0ULL; acc[i][1] = 0ULL; }

    for (int k0 = 0; k0 < K; k0 += 16) {
        const float* Ab;
        int kloc;
        if (k0 < 128) { Ab = A1; kloc = k0; } else { Ab = A2; kloc = k0 - 128; }
        float4 av = *(const float4*)&Ab[(size_t)(bm + arow) * 128 + kloc + ak4];
        *(float4*)&As[arow][ak4] = av;
        float4 bv = *(const float4*)&B[(size_t)(k0 + bk) * N + bn + bn4];
        *(float4*)&Bs[bk][bn4] = bv;
        __syncthreads();
#pragma unroll
        for (int kk = 0; kk < 16; kk++) {
            ull b01 = *(const ull*)&Bs[kk][tx * 4];
            ull b23 = *(const ull*)&Bs[kk][tx * 4 + 2];
#pragma unroll
            for (int i = 0; i < 4; i++) {
                float a = As[ty * 4 + i][kk];
                ull ap = packf2(a, a);
                ffma2(acc[i][0], ap, b01);
                ffma2(acc[i][1], ap, b23);
            }
        }
        __syncthreads();
    }

#pragma unroll
    for (int i = 0; i < 4; i++) {
        float2 c01 = unpackf2(acc[i][0]);
        float2 c23 = unpackf2(acc[i][1]);
        float4 ov;
        ov.x = c01.x + bias[bn + tx * 4 + 0];
        ov.y = c01.y + bias[bn + tx * 4 + 1];
        ov.z = c23.x + bias[bn + tx * 4 + 2];
        ov.w = c23.y + bias[bn + tx * 4 + 3];
        if (epi == 0) {
            ov.x = expf(-fmaxf(ov.x, 0.0f));
            ov.y = expf(-fmaxf(ov.y, 0.0f));
            ov.z = expf(-fmaxf(ov.z, 0.0f));
            ov.w = expf(-fmaxf(ov.w, 0.0f));
        }
        *(float4*)&C[(size_t)(bm + ty * 4 + i) * N + bn + tx * 4] = ov;
    }
}

__global__ void __launch_bounds__(256) gemm_merged(
    const float* __restrict__ deltas, const float* __restrict__ masks,
    const float* __restrict__ WthT, const float* __restrict__ bth,
    const float* __restrict__ WtxT, const float* __restrict__ btx,
    const float* __restrict__ WkBot, const float* __restrict__ bl,
    float* __restrict__ Gh, float* __restrict__ Gx, float* __restrict__ Gm)
{
    int bm = blockIdx.x * 64;
    int y = blockIdx.y;
    if (y < 2)       gemm_body(deltas, nullptr, WthT, bth, Gh, 128, 128, 0, bm, y * 64);
    else if (y < 4)  gemm_body(deltas, nullptr, WtxT, btx, Gx, 128, 128, 0, bm, (y - 2) * 64);
    else             gemm_body(masks,  nullptr, WkBot, bl, Gm, 512, 128, 1, bm, (y - 4) * 64);
}

__global__ void __launch_bounds__(256) gemm_beta(
    const float* __restrict__ Gx, const float* __restrict__ masks,
    const float* __restrict__ Wwc, const float* __restrict__ bwc,
    float* __restrict__ Beta)
{
    gemm_body(Gx, masks, Wwc, bwc, Beta, 128, 256, 1, blockIdx.x * 64, blockIdx.y * 64);
}

// ---------------------------------------------------------------------------
// Sequential recurrence: 128 CTAs x 4 rows x 512 threads, k-split partials.
//   B/C: thread (j, g) covers k in [32g, 32g+32) for all 4 rows -> each
//        weight element read ONCE per CTA (wf-optimal). Reduce by (q, j).
//   E:   thread (c=tid&255, g2=tid>>8) covers columns {c, c+256}, a k-half,
//        all 4 rows. Partials in SMEM; Phase F reduces its own 4 gates.
//   Cell state c lives in a register. Decay folded into F (gamma(t+1)).
// ---------------------------------------------------------------------------
__global__ void __launch_bounds__(512, 1) seq_kernel(
    const float* __restrict__ values, const float* __restrict__ masks,
    const float* __restrict__ WhrQ_g, const float* __restrict__ bhr,
    const float* __restrict__ bfr,    const float* __restrict__ WfrQ_g,
    const float* __restrict__ Gh,     const float* __restrict__ Beta,
    const float* __restrict__ Gm,     const float* __restrict__ den,
    const float* __restrict__ Wd,     const float* __restrict__ bd,
    const float* __restrict__ Wo,     const float* __restrict__ bo,
    const float* __restrict__ WgQ,
    float* __restrict__ out_pred, float* __restrict__ out_imp,
    float* __restrict__ out_loss)
{
    extern __shared__ float sm[];
    float* sWhrQ = sm;                 // 16384
    float* sWfrQ = sm + 16384;         // 16384
    float* sh    = sm + 32768;         // 512
    float* sxc   = sm + 33280;         // 512
    float* scc   = sm + 33792;         // 512
    float* pp    = sm + 34304;         // 4096 partials (pB/pC: [g][r][j]; pE: [g2][r][n])
    float* sbhr  = sm + 38400;         // 128
    float* sbfr  = sm + 38528;         // 128
    // total 38656 floats = 154,624 B

    const int tid = threadIdx.x;
    const int b0 = blockIdx.x * 4;

    for (int i = tid; i < 16384; i += 512) { sWhrQ[i] = WhrQ_g[i]; sWfrQ[i] = WfrQ_g[i]; }
    if (tid < 128) { sbhr[tid] = bhr[tid]; sbfr[tid] = bfr[tid]; }
    if (tid < 512) sh[tid] = 0.0f;

    const int j  = tid & 127;
    const int q  = tid >> 7;            // row (reduce phases) == k-group g (partials)
    const int ec = tid & 255;           // E column base
    const int eg = tid >> 8;            // E k-half (0: cc/Wk_top, 1: h/Wr)
    const size_t rowbase = (size_t)(b0 + q) * T_STEPS;

    float creg = 0.0f;                  // LSTM cell state (thread-private)
    float lsum = 0.0f;

    // current-step (t=0) operands
    float cx = values[rowbase * DD + j];
    float cm = masks[rowbase * DD + j];
    float cb = Beta[rowbase * DD + j];
    float cden = den[0];

    for (int t = 0; t < T_STEPS; t++) {
        __syncthreads();                                   // S1: sh/pp ready

        // Gm gates for this thread's row q, columns j+128m (coalesced)
        float gmv[4];
#pragma unroll
        for (int mm = 0; mm < 4; mm++)
            gmv[mm] = Gm[(rowbase + t) * 512 + j + 128 * mm];

        // prefetch next step
        int tn = (t + 1 < T_STEPS) ? (t + 1) : (T_STEPS - 1);
        float nx = values[(rowbase + tn) * DD + j];
        float nm = masks[(rowbase + tn) * DD + j];
        float ng = Gh[(rowbase + tn) * DD + j];            // gamma(t+1)
        float nb = Beta[(rowbase + tn) * DD + j];
        float nden = den[tn];

        // --- Phase B partials: k in [32q, 32q+32), all 4 rows ---
        {
            ull a0 = 0ULL, a1 = 0ULL, a2 = 0ULL, a3 = 0ULL;
#pragma unroll
            for (int k4 = 0; k4 < 8; k4++) {
                ulonglong2 w = *(const ulonglong2*)&sWhrQ[(q * 8 + k4) * 512 + j * 4];
                int ko = q * 32 + k4 * 4;
                ulonglong2 v0 = *(const ulonglong2*)&sh[0 * 128 + ko];
                ulonglong2 v1 = *(const ulonglong2*)&sh[1 * 128 + ko];
                ulonglong2 v2 = *(const ulonglong2*)&sh[2 * 128 + ko];
                ulonglong2 v3 = *(const ulonglong2*)&sh[3 * 128 + ko];
                ffma2(a0, v0.x, w.x); ffma2(a0, v0.y, w.y);
                ffma2(a1, v1.x, w.x); ffma2(a1, v1.y, w.y);
                ffma2(a2, v2.x, w.x); ffma2(a2, v2.y, w.y);
                ffma2(a3, v3.x, w.x); ffma2(a3, v3.y, w.y);
            }
            pp[q * 512 + 0 * 128 + j] = hsum2(a0);
            pp[q * 512 + 1 * 128 + j] = hsum2(a1);
            pp[q * 512 + 2 * 128 + j] = hsum2(a2);
            pp[q * 512 + 3 * 128 + j] = hsum2(a3);
        }
        __syncthreads();                                   // S2a

        // --- Phase B reduce (thread (q, j)) ---
        float xh = sbhr[j] + pp[0 * 512 + q * 128 + j] + pp[1 * 512 + q * 128 + j]
                           + pp[2 * 512 + q * 128 + j] + pp[3 * 512 + q * 128 + j];
        float x = cx, m = cm;
        float rd = 1.0f / cden;
        float xc = m * x + (1.0f - m) * xh;
        sxc[q * 128 + j] = xc;
        lsum += fabsf(x - xh) * m * rd;
        __syncthreads();                                   // S2b

        // --- Phase C partials ---
        {
            ull a0 = 0ULL, a1 = 0ULL, a2 = 0ULL, a3 = 0ULL;
#pragma unroll
            for (int k4 = 0; k4 < 8; k4++) {
                ulonglong2 w = *(const ulonglong2*)&sWfrQ[(q * 8 + k4) * 512 + j * 4];
                int ko = q * 32 + k4 * 4;
                ulonglong2 v0 = *(const ulonglong2*)&sxc[0 * 128 + ko];
                ulonglong2 v1 = *(const ulonglong2*)&sxc[1 * 128 + ko];
                ulonglong2 v2 = *(const ulonglong2*)&sxc[2 * 128 + ko];
                ulonglong2 v3 = *(const ulonglong2*)&sxc[3 * 128 + ko];
                ffma2(a0, v0.x, w.x); ffma2(a0, v0.y, w.y);
                ffma2(a1, v1.x, w.x); ffma2(a1, v1.y, w.y);
                ffma2(a2, v2.x, w.x); ffma2(a2, v2.y, w.y);
                ffma2(a3, v3.x, w.x); ffma2(a3, v3.y, w.y);
            }
            pp[q * 512 + 0 * 128 + j] = hsum2(a0);
            pp[q * 512 + 1 * 128 + j] = hsum2(a1);
            pp[q * 512 + 2 * 128 + j] = hsum2(a2);
            pp[q * 512 + 3 * 128 + j] = hsum2(a3);
        }
        __syncthreads();                                   // S3a

        // --- Phase C reduce + D (thread (q, j)) ---
        float zh = sbfr[j] + pp[0 * 512 + q * 128 + j] + pp[1 * 512 + q * 128 + j]
                           + pp[2 * 512 + q * 128 + j] + pp[3 * 512 + q * 128 + j];
        lsum += fabsf(x - zh) * m * rd;
        float be = cb;
        float ch = be * zh + (1.0f - be) * xh;
        lsum += fabsf(x - ch) * m * rd;
        float cc = m * x + (1.0f - m) * ch;
        scc[q * 128 + j] = cc;
        out_imp[(rowbase + t) * DD + j] = cc;
        __syncthreads();                                   // S3b

        // --- Phase E partials: cols {ec, ec+256}, k-half eg, 4 rows ---
        {
            const float* src = (eg == 0) ? scc : sh;       // k<128: cc@Wk_top, else h@Wr
            const float* wbase = WgQ + (size_t)(eg * 32) * 2048;
            ull e0 = 0ULL, e1 = 0ULL, e2 = 0ULL, e3 = 0ULL;
            ull e4 = 0ULL, e5 = 0ULL, e6 = 0ULL, e7 = 0ULL;
#pragma unroll 4
            for (int i = 0; i < 32; i++) {
                ulonglong2 wA = *(const ulonglong2*)&wbase[(size_t)i * 2048 + ec * 4];
                ulonglong2 wB = *(const ulonglong2*)&wbase[(size_t)i * 2048 + (ec + 256) * 4];
                ulonglong2 v0 = *(const ulonglong2*)&src[0 * 128 + i * 4];
                ulonglong2 v1 = *(const ulonglong2*)&src[1 * 128 + i * 4];
                ulonglong2 v2 = *(const ulonglong2*)&src[2 * 128 + i * 4];
                ulonglong2 v3 = *(const ulonglong2*)&src[3 * 128 + i * 4];
                ffma2(e0, v0.x, wA.x); ffma2(e0, v0.y, wA.y);
                ffma2(e1, v1.x, wA.x); ffma2(e1, v1.y, wA.y);
                ffma2(e2, v2.x, wA.x); ffma2(e2, v2.y, wA.y);
                ffma2(e3, v3.x, wA.x); ffma2(e3, v3.y, wA.y);
                ffma2(e4, v0.x, wB.x); ffma2(e4, v0.y, wB.y);
                ffma2(e5, v1.x, wB.x); ffma2(e5, v1.y, wB.y);
                ffma2(e6, v2.x, wB.x); ffma2(e6, v2.y, wB.y);
                ffma2(e7, v3.x, wB.x); ffma2(e7, v3.y, wB.y);
            }
            // pE[eg][r][n] = pp[eg*2048 + r*512 + n]
            pp[eg * 2048 + 0 * 512 + ec] = hsum2(e0);
            pp[eg * 2048 + 1 * 512 + ec] = hsum2(e1);
            pp[eg * 2048 + 2 * 512 + ec] = hsum2(e2);
            pp[eg * 2048 + 3 * 512 + ec] = hsum2(e3);
            pp[eg * 2048 + 0 * 512 + ec + 256] = hsum2(e4);
            pp[eg * 2048 + 1 * 512 + ec + 256] = hsum2(e5);
            pp[eg * 2048 + 2 * 512 + ec + 256] = hsum2(e6);
            pp[eg * 2048 + 3 * 512 + ec + 256] = hsum2(e7);
        }
        __syncthreads();                                   // S4

        // --- Phase F: reduce own gates + LSTM update + decay(t+1) ---
        {
            float gi = gmv[0] + pp[q * 512 + j]        + pp[2048 + q * 512 + j];
            float gf = gmv[1] + pp[q * 512 + 128 + j]  + pp[2048 + q * 512 + 128 + j];
            float gg = gmv[2] + pp[q * 512 + 256 + j]  + pp[2048 + q * 512 + 256 + j];
            float go = gmv[3] + pp[q * 512 + 384 + j]  + pp[2048 + q * 512 + 384 + j];
            float cn = sigmoidf_(gf) * creg + sigmoidf_(gi) * tanhf(gg);
            creg = cn;
            float ho = sigmoidf_(go) * tanhf(cn);
            float dec = (t == T_STEPS - 1) ? 1.0f : ng;    // final h undecayed
            sh[q * 128 + j] = ho * dec;
        }

        cx = nx; cm = nm; cb = nb; cden = nden;
    }

    __syncthreads();

    // --- custom_loss ---
    pp[q * 128 + j] = lsum;
    __syncthreads();
    if (tid < 4) {
        float s = 0.0f;
        for (int k = 0; k < 128; k++) s += pp[tid * 128 + k];
        out_loss[b0 + tid] = s * (1.0f / T_STEPS);
    }
    __syncthreads();

    // --- predictions = relu(h @ Wd + bd) @ Wo + bo ---
    float pa = bd[j];
    for (int k = 0; k < 128; k++)
        pa = fmaf(sh[q * 128 + k], Wd[k * DD + j], pa);
    pp[q * 128 + j] = fmaxf(pa, 0.0f) * Wo[j];
    __syncthreads();
    if (tid < 4) {
        float s = 0.0f;
        for (int k = 0; k < 128; k++) s += pp[tid * 128 + k];
        out_pred[b0 + tid] = s + bo[0];
    }
}

// ---------------------------------------------------------------------------
extern "C" void kernel_launch(void* const* d_in, const int* in_sizes, int n_in,
                              void* d_out, int out_size)
{
    const float* values = (const float*)d_in[0];
    const float* masks  = (const float*)d_in[1];
    const float* deltas = (const float*)d_in[2];
    const float* Wth    = (const float*)d_in[3];
    const float* bth    = (const float*)d_in[4];
    const float* Wtx    = (const float*)d_in[5];
    const float* btx    = (const float*)d_in[6];
    const float* Whr    = (const float*)d_in[7];
    const float* bhr    = (const float*)d_in[8];
    const float* Wfr    = (const float*)d_in[9];
    const float* bfr    = (const float*)d_in[10];
    const float* Wwc    = (const float*)d_in[11];
    const float* bwc    = (const float*)d_in[12];
    const float* Wk     = (const float*)d_in[13];
    const float* Wr     = (const float*)d_in[14];
    const float* bl     = (const float*)d_in[15];
    const float* Wd     = (const float*)d_in[16];
    const float* bd     = (const float*)d_in[17];
    const float* Wo     = (const float*)d_in[18];
    const float* bo     = (const float*)d_in[19];

    float *pGh, *pGx, *pBeta, *pGm, *pDen, *pWthT, *pWtxT, *pWhrQ, *pWfrQ, *pWgQ;
    cudaGetSymbolAddress((void**)&pGh,   g_Gh);
    cudaGetSymbolAddress((void**)&pGx,   g_Gx);
    cudaGetSymbolAddress((void**)&pBeta, g_Beta);
    cudaGetSymbolAddress((void**)&pGm,   g_Gm);
    cudaGetSymbolAddress((void**)&pDen,  g_den);
    cudaGetSymbolAddress((void**)&pWthT, g_WthT);
    cudaGetSymbolAddress((void**)&pWtxT, g_WtxT);
    cudaGetSymbolAddress((void**)&pWhrQ, g_WhrQ);
    cudaGetSymbolAddress((void**)&pWfrQ, g_WfrQ);
    cudaGetSymbolAddress((void**)&pWgQ,  g_WgQ);

    // Launch 0: prep (incl. denom)
    prep_weights<<<512, 256>>>(Wth, Wtx, Whr, Wfr, Wk, Wr, masks,
                               pWthT, pWtxT, pWhrQ, pWfrQ, pWgQ, pDen);

    // Launch 1: merged GEMM (Gh, Gx, Gm)
    dim3 gm(1024, 12);
    gemm_merged<<<gm, 256>>>(deltas, masks, pWthT, bth, pWtxT, btx,
                             Wk + 128 * 512, bl, pGh, pGx, pGm);

    // Launch 2: Beta (consumes Gx)
    dim3 gb(1024, 2);
    gemm_beta<<<gb, 256>>>(pGx, masks, Wwc, bwc, pBeta);

    // Launch 3: sequential recurrence
    float* out = (float*)d_out;
    const size_t SMEM = (size_t)38656 * sizeof(float);   // 154,624 B
    cudaFuncSetAttribute(seq_kernel, cudaFuncAttributeMaxDynamicSharedMemorySize, (int)SMEM);
    seq_kernel<<<128, 512, SMEM>>>(values, masks, pWhrQ, bhr, bfr, pWfrQ,
                                   pGh, pBeta, pGm, pDen,
                                   Wd, bd, Wo, bo, pWgQ,
                                   out,                     // predictions [512]
                                   out + 512,               // imputations [512*128*128]
                                   out + 512 + 8388608);    // custom_loss [512]
}

// round 9
// speedup vs baseline: 1.9126x; 1.0647x over previous
#include <cuda_runtime.h>
#include <cuda_bf16.h>
#include <cuda_fp16.h>
#include <math.h>

// ---------------------------------------------------------------------------
// RITS / BRITS-style recurrent imputation. B=512, T=128, D=H=128.
// Launches: prep(+denom), mergedGEMM(Gh,Gx,Gm), betaGEMM, seq  (4 total)
// seq: 128 CTAs x 4 rows x 512 threads, k-split partials (R8 structure).
// R9: gate weights Wg streamed as fp16 (halves the dominant L1tex wf stream);
//     all math and all other weights remain fp32.
// ---------------------------------------------------------------------------

#define T_STEPS  128
#define DD       128

typedef unsigned long long ull;

__device__ __align__(16) float g_Gh[8388608];     // [BT, 128]
__device__ __align__(16) float g_Gx[8388608];     // [BT, 128]
__device__ __align__(16) float g_Beta[8388608];   // [BT, 128]
__device__ __align__(16) float g_Gm[33554432];    // [BT, 512]
__device__ __align__(16) float g_den[128];
__device__ __align__(16) float g_WthT[16384];
__device__ __align__(16) float g_WtxT[16384];
__device__ __align__(16) float g_WhrQ[16384];     // [32 k4][128 j][4 e]  fp32
__device__ __align__(16) float g_WfrQ[16384];     // [32 k4][128 j][4 e]  fp32
__device__ __align__(16) __half g_Wg16[131072];   // [32 k8][512 n][8 e]  fp16

__device__ __forceinline__ float sigmoidf_(float x) { return 1.0f / (1.0f + expf(-x)); }

__device__ __forceinline__ void ffma2(ull& d, ull a, ull b) {
    asm("fma.rn.f32x2 %0, %1, %2, %0;" : "+l"(d) : "l"(a), "l"(b));
}
__device__ __forceinline__ ull packf2(float a, float b) {
    ull u; asm("mov.b64 %0, {%1, %2};" : "=l"(u) : "f"(a), "f"(b)); return u;
}
__device__ __forceinline__ float hsum2(ull u) {
    float x, y; asm("mov.b64 {%0, %1}, %2;" : "=f"(x), "=f"(y) : "l"(u));
    return x + y;
}
__device__ __forceinline__ float2 unpackf2(ull u) {
    float2 r; asm("mov.b64 {%0, %1}, %2;" : "=f"(r.x), "=f"(r.y) : "l"(u));
    return r;
}
// 8 fp16 weights -> 4 packed f32x2 operands
__device__ __forceinline__ void cvt8(uint4 w, ull& u0, ull& u1, ull& u2, ull& u3) {
    const __half2* h = reinterpret_cast<const __half2*>(&w);
    float2 f0 = __half22float2(h[0]);
    float2 f1 = __half22float2(h[1]);
    float2 f2 = __half22float2(h[2]);
    float2 f3 = __half22float2(h[3]);
    u0 = packf2(f0.x, f0.y);
    u1 = packf2(f1.x, f1.y);
    u2 = packf2(f2.x, f2.y);
    u3 = packf2(f3.x, f3.y);
}

// ---------------------------------------------------------------------------
// Prep: transposes + quad-k repacks + fp16 gate weights + denom
// ---------------------------------------------------------------------------
__global__ void prep_weights(const float* __restrict__ Wth, const float* __restrict__ Wtx,
                             const float* __restrict__ Whr, const float* __restrict__ Wfr,
                             const float* __restrict__ Wk,  const float* __restrict__ Wr,
                             const float* __restrict__ masks,
                             float* __restrict__ WthT, float* __restrict__ WtxT,
                             float* __restrict__ WhrQ, float* __restrict__ WfrQ,
                             __half* __restrict__ Wg16, float* __restrict__ den)
{
    int idx = blockIdx.x * blockDim.x + threadIdx.x;
    if (idx < 16384) {
        int k = idx >> 7, j = idx & 127;
        WthT[idx] = Wth[j * 128 + k];
        WtxT[idx] = Wtx[j * 128 + k];
        int k4 = idx >> 9, rem = idx & 511, jj = rem >> 2, e = rem & 3;
        int kk = 4 * k4 + e;
        WhrQ[idx] = Whr[kk * 128 + jj];
        WfrQ[idx] = Wfr[jj * 128 + kk];
    }
    if (idx < 131072) {
        // Wg16[(k8*512 + n)*8 + e], global k = k8*8 + e; Wg = [Wk_top; Wr]
        int k8 = idx >> 12, rem = idx & 4095, n = rem >> 3, e = rem & 7;
        int k = k8 * 8 + e;
        float v = (k < 128) ? Wk[k * 512 + n] : Wr[(k - 128) * 512 + n];
        Wg16[idx] = __float2half(v);
    }
    if (blockIdx.x < 128) {
        int t = blockIdx.x;
        float s = 0.0f;
        for (int i = threadIdx.x; i < 512 * 128; i += blockDim.x) {
            int b = i >> 7, d = i & 127;
            s += masks[((size_t)b * T_STEPS + t) * DD + d];
        }
        __shared__ float red[256];
        red[threadIdx.x] = s;
        __syncthreads();
        for (int off = 128; off > 0; off >>= 1) {
            if (threadIdx.x < off) red[threadIdx.x] += red[threadIdx.x + off];
            __syncthreads();
        }
        if (threadIdx.x == 0) den[t] = red[0] + 1e-6f;
    }
}

// ---------------------------------------------------------------------------
// GEMM body (precompute), packed f32x2 FMAs. Unchanged.
// ---------------------------------------------------------------------------
__device__ __forceinline__ void gemm_body(
    const float* __restrict__ A1, const float* __restrict__ A2,
    const float* __restrict__ B, const float* __restrict__ bias,
    float* __restrict__ C, int N, int K, int epi, int bm, int bn)
{
    __shared__ float As[64][16];
    __shared__ float Bs[16][64];

    const int tid = threadIdx.x;
    const int tx = tid & 15;
    const int ty = tid >> 4;
    const int arow = tid >> 2;
    const int ak4 = (tid & 3) * 4;
    const int bk = tid >> 4;
    const int bn4 = (tid & 15) * 4;

    ull acc[4][2];
#pragma unroll
    for (int i = 0; i < 4; i++) { acc[i][0] = 0ULL; acc[i][1] = 0ULL; }

    for (int k0 = 0; k0 < K; k0 += 16) {
        const float* Ab;
        int kloc;
        if (k0 < 128) { Ab = A1; kloc = k0; } else { Ab = A2; kloc = k0 - 128; }
        float4 av = *(const float4*)&Ab[(size_t)(bm + arow) * 128 + kloc + ak4];
        *(float4*)&As[arow][ak4] = av;
        float4 bv = *(const float4*)&B[(size_t)(k0 + bk) * N + bn + bn4];
        *(float4*)&Bs[bk][bn4] = bv;
        __syncthreads();
#pragma unroll
        for (int kk = 0; kk < 16; kk++) {
            ull b01 = *(const ull*)&Bs[kk][tx * 4];
            ull b23 = *(const ull*)&Bs[kk][tx * 4 + 2];
#pragma unroll
            for (int i = 0; i < 4; i++) {
                float a = As[ty * 4 + i][kk];
                ull ap = packf2(a, a);
                ffma2(acc[i][0], ap, b01);
                ffma2(acc[i][1], ap, b23);
            }
        }
        __syncthreads();
    }

#pragma unroll
    for (int i = 0; i < 4; i++) {
        float2 c01 = unpackf2(acc[i][0]);
        float2 c23 = unpackf2(acc[i][1]);
        float4 ov;
        ov.x = c01.x + bias[bn + tx * 4 + 0];
        ov.y = c01.y + bias[bn + tx * 4 + 1];
        ov.z = c23.x + bias[bn + tx * 4 + 2];
        ov.w = c23.y + bias[bn + tx * 4 + 3];
        if (epi == 0) {
            ov.x = expf(-fmaxf(ov.x, 0.0f));
            ov.y = expf(-fmaxf(ov.y, 0.0f));
            ov.z = expf(-fmaxf(ov.z, 0.0f));
            ov.w = expf(-fmaxf(ov.w, 0.0f));
        }
        *(float4*)&C[(size_t)(bm + ty * 4 + i) * N + bn + tx * 4] = ov;
    }
}

__global__ void __launch_bounds__(256) gemm_merged(
    const float* __restrict__ deltas, const float* __restrict__ masks,
    const float* __restrict__ WthT, const float* __restrict__ bth,
    const float* __restrict__ WtxT, const float* __restrict__ btx,
    const float* __restrict__ WkBot, const float* __restrict__ bl,
    float* __restrict__ Gh, float* __restrict__ Gx, float* __restrict__ Gm)
{
    int bm = blockIdx.x * 64;
    int y = blockIdx.y;
    if (y < 2)       gemm_body(deltas, nullptr, WthT, bth, Gh, 128, 128, 0, bm, y * 64);
    else if (y < 4)  gemm_body(deltas, nullptr, WtxT, btx, Gx, 128, 128, 0, bm, (y - 2) * 64);
    else             gemm_body(masks,  nullptr, WkBot, bl, Gm, 512, 128, 1, bm, (y - 4) * 64);
}

__global__ void __launch_bounds__(256) gemm_beta(
    const float* __restrict__ Gx, const float* __restrict__ masks,
    const float* __restrict__ Wwc, const float* __restrict__ bwc,
    float* __restrict__ Beta)
{
    gemm_body(Gx, masks, Wwc, bwc, Beta, 128, 256, 1, blockIdx.x * 64, blockIdx.y * 64);
}

// ---------------------------------------------------------------------------
// Sequential recurrence: 128 CTAs x 4 rows x 512 threads, k-split partials.
// Phase E weights fp16 (cvt to fp32 on the ALU pipe, FFMA2 math unchanged).
// ---------------------------------------------------------------------------
__global__ void __launch_bounds__(512, 1) seq_kernel(
    const float* __restrict__ values, const float* __restrict__ masks,
    const float* __restrict__ WhrQ_g, const float* __restrict__ bhr,
    const float* __restrict__ bfr,    const float* __restrict__ WfrQ_g,
    const float* __restrict__ Gh,     const float* __restrict__ Beta,
    const float* __restrict__ Gm,     const float* __restrict__ den,
    const float* __restrict__ Wd,     const float* __restrict__ bd,
    const float* __restrict__ Wo,     const float* __restrict__ bo,
    const __half* __restrict__ Wg16,
    float* __restrict__ out_pred, float* __restrict__ out_imp,
    float* __restrict__ out_loss)
{
    extern __shared__ float sm[];
    float* sWhrQ = sm;                 // 16384
    float* sWfrQ = sm + 16384;         // 16384
    float* sh    = sm + 32768;         // 512
    float* sxc   = sm + 33280;         // 512
    float* scc   = sm + 33792;         // 512
    float* pp    = sm + 34304;         // 4096 partials
    float* sbhr  = sm + 38400;         // 128
    float* sbfr  = sm + 38528;         // 128
    // total 38656 floats = 154,624 B

    const int tid = threadIdx.x;
    const int b0 = blockIdx.x * 4;

    for (int i = tid; i < 16384; i += 512) { sWhrQ[i] = WhrQ_g[i]; sWfrQ[i] = WfrQ_g[i]; }
    if (tid < 128) { sbhr[tid] = bhr[tid]; sbfr[tid] = bfr[tid]; }
    if (tid < 512) sh[tid] = 0.0f;

    const int j  = tid & 127;
    const int q  = tid >> 7;            // row (reduce phases) == k-group (partials)
    const int ec = tid & 255;           // E column base
    const int eg = tid >> 8;            // E k-half (0: cc/Wk_top, 1: h/Wr)
    const size_t rowbase = (size_t)(b0 + q) * T_STEPS;

    float creg = 0.0f;                  // LSTM cell state
    float lsum = 0.0f;

    float cx = values[rowbase * DD + j];
    float cm = masks[rowbase * DD + j];
    float cb = Beta[rowbase * DD + j];
    float cden = den[0];

    for (int t = 0; t < T_STEPS; t++) {
        __syncthreads();                                   // S1

        float gmv[4];
#pragma unroll
        for (int mm = 0; mm < 4; mm++)
            gmv[mm] = Gm[(rowbase + t) * 512 + j + 128 * mm];

        int tn = (t + 1 < T_STEPS) ? (t + 1) : (T_STEPS - 1);
        float nx = values[(rowbase + tn) * DD + j];
        float nm = masks[(rowbase + tn) * DD + j];
        float ng = Gh[(rowbase + tn) * DD + j];
        float nb = Beta[(rowbase + tn) * DD + j];
        float nden = den[tn];

        // --- Phase B partials: k in [32q, 32q+32), all 4 rows ---
        {
            ull a0 = 0ULL, a1 = 0ULL, a2 = 0ULL, a3 = 0ULL;
#pragma unroll
            for (int k4 = 0; k4 < 8; k4++) {
                ulonglong2 w = *(const ulonglong2*)&sWhrQ[(q * 8 + k4) * 512 + j * 4];
                int ko = q * 32 + k4 * 4;
                ulonglong2 v0 = *(const ulonglong2*)&sh[0 * 128 + ko];
                ulonglong2 v1 = *(const ulonglong2*)&sh[1 * 128 + ko];
                ulonglong2 v2 = *(const ulonglong2*)&sh[2 * 128 + ko];
                ulonglong2 v3 = *(const ulonglong2*)&sh[3 * 128 + ko];
                ffma2(a0, v0.x, w.x); ffma2(a0, v0.y, w.y);
                ffma2(a1, v1.x, w.x); ffma2(a1, v1.y, w.y);
                ffma2(a2, v2.x, w.x); ffma2(a2, v2.y, w.y);
                ffma2(a3, v3.x, w.x); ffma2(a3, v3.y, w.y);
            }
            pp[q * 512 + 0 * 128 + j] = hsum2(a0);
            pp[q * 512 + 1 * 128 + j] = hsum2(a1);
            pp[q * 512 + 2 * 128 + j] = hsum2(a2);
            pp[q * 512 + 3 * 128 + j] = hsum2(a3);
        }
        __syncthreads();                                   // S2a

        float xh = sbhr[j] + pp[0 * 512 + q * 128 + j] + pp[1 * 512 + q * 128 + j]
                           + pp[2 * 512 + q * 128 + j] + pp[3 * 512 + q * 128 + j];
        float x = cx, m = cm;
        float rd = 1.0f / cden;
        float xc = m * x + (1.0f - m) * xh;
        sxc[q * 128 + j] = xc;
        lsum += fabsf(x - xh) * m * rd;
        __syncthreads();                                   // S2b

        // --- Phase C partials ---
        {
            ull a0 = 0ULL, a1 = 0ULL, a2 = 0ULL, a3 = 0ULL;
#pragma unroll
            for (int k4 = 0; k4 < 8; k4++) {
                ulonglong2 w = *(const ulonglong2*)&sWfrQ[(q * 8 + k4) * 512 + j * 4];
                int ko = q * 32 + k4 * 4;
                ulonglong2 v0 = *(const ulonglong2*)&sxc[0 * 128 + ko];
                ulonglong2 v1 = *(const ulonglong2*)&sxc[1 * 128 + ko];
                ulonglong2 v2 = *(const ulonglong2*)&sxc[2 * 128 + ko];
                ulonglong2 v3 = *(const ulonglong2*)&sxc[3 * 128 + ko];
                ffma2(a0, v0.x, w.x); ffma2(a0, v0.y, w.y);
                ffma2(a1, v1.x, w.x); ffma2(a1, v1.y, w.y);
                ffma2(a2, v2.x, w.x); ffma2(a2, v2.y, w.y);
                ffma2(a3, v3.x, w.x); ffma2(a3, v3.y, w.y);
            }
            pp[q * 512 + 0 * 128 + j] = hsum2(a0);
            pp[q * 512 + 1 * 128 + j] = hsum2(a1);
            pp[q * 512 + 2 * 128 + j] = hsum2(a2);
            pp[q * 512 + 3 * 128 + j] = hsum2(a3);
        }
        __syncthreads();                                   // S3a

        float zh = sbfr[j] + pp[0 * 512 + q * 128 + j] + pp[1 * 512 + q * 128 + j]
                           + pp[2 * 512 + q * 128 + j] + pp[3 * 512 + q * 128 + j];
        lsum += fabsf(x - zh) * m * rd;
        float be = cb;
        float ch = be * zh + (1.0f - be) * xh;
        lsum += fabsf(x - ch) * m * rd;
        float cc = m * x + (1.0f - m) * ch;
        scc[q * 128 + j] = cc;
        out_imp[(rowbase + t) * DD + j] = cc;
        __syncthreads();                                   // S3b

        // --- Phase E partials: cols {ec, ec+256}, k-half eg, 4 rows, fp16 W ---
        {
            const float* src = (eg == 0) ? scc : sh;
            const __half* w16 = Wg16 + (size_t)eg * 16 * 512 * 8;
            ull e0 = 0ULL, e1 = 0ULL, e2 = 0ULL, e3 = 0ULL;
            ull e4 = 0ULL, e5 = 0ULL, e6 = 0ULL, e7 = 0ULL;
#pragma unroll 2
            for (int i = 0; i < 16; i++) {
                uint4 wa_raw = *(const uint4*)&w16[((size_t)i * 512 + ec) * 8];
                uint4 wb_raw = *(const uint4*)&w16[((size_t)i * 512 + ec + 256) * 8];
                ull wa0, wa1, wa2, wa3, wb0, wb1, wb2, wb3;
                cvt8(wa_raw, wa0, wa1, wa2, wa3);
                cvt8(wb_raw, wb0, wb1, wb2, wb3);
                int ko = i * 8;
                ulonglong2 v0L = *(const ulonglong2*)&src[0 * 128 + ko];
                ulonglong2 v0H = *(const ulonglong2*)&src[0 * 128 + ko + 4];
                ulonglong2 v1L = *(const ulonglong2*)&src[1 * 128 + ko];
                ulonglong2 v1H = *(const ulonglong2*)&src[1 * 128 + ko + 4];
                ulonglong2 v2L = *(const ulonglong2*)&src[2 * 128 + ko];
                ulonglong2 v2H = *(const ulonglong2*)&src[2 * 128 + ko + 4];
                ulonglong2 v3L = *(const ulonglong2*)&src[3 * 128 + ko];
                ulonglong2 v3H = *(const ulonglong2*)&src[3 * 128 + ko + 4];
                ffma2(e0, v0L.x, wa0); ffma2(e0, v0L.y, wa1); ffma2(e0, v0H.x, wa2); ffma2(e0, v0H.y, wa3);
                ffma2(e1, v1L.x, wa0); ffma2(e1, v1L.y, wa1); ffma2(e1, v1H.x, wa2); ffma2(e1, v1H.y, wa3);
                ffma2(e2, v2L.x, wa0); ffma2(e2, v2L.y, wa1); ffma2(e2, v2H.x, wa2); ffma2(e2, v2H.y, wa3);
                ffma2(e3, v3L.x, wa0); ffma2(e3, v3L.y, wa1); ffma2(e3, v3H.x, wa2); ffma2(e3, v3H.y, wa3);
                ffma2(e4, v0L.x, wb0); ffma2(e4, v0L.y, wb1); ffma2(e4, v0H.x, wb2); ffma2(e4, v0H.y, wb3);
                ffma2(e5, v1L.x, wb0); ffma2(e5, v1L.y, wb1); ffma2(e5, v1H.x, wb2); ffma2(e5, v1H.y, wb3);
                ffma2(e6, v2L.x, wb0); ffma2(e6, v2L.y, wb1); ffma2(e6, v2H.x, wb2); ffma2(e6, v2H.y, wb3);
                ffma2(e7, v3L.x, wb0); ffma2(e7, v3L.y, wb1); ffma2(e7, v3H.x, wb2); ffma2(e7, v3H.y, wb3);
            }
            pp[eg * 2048 + 0 * 512 + ec] = hsum2(e0);
            pp[eg * 2048 + 1 * 512 + ec] = hsum2(e1);
            pp[eg * 2048 + 2 * 512 + ec] = hsum2(e2);
            pp[eg * 2048 + 3 * 512 + ec] = hsum2(e3);
            pp[eg * 2048 + 0 * 512 + ec + 256] = hsum2(e4);
            pp[eg * 2048 + 1 * 512 + ec + 256] = hsum2(e5);
            pp[eg * 2048 + 2 * 512 + ec + 256] = hsum2(e6);
            pp[eg * 2048 + 3 * 512 + ec + 256] = hsum2(e7);
        }
        __syncthreads();                                   // S4

        // --- Phase F: reduce own gates + LSTM update + decay(t+1) ---
        {
            float gi = gmv[0] + pp[q * 512 + j]        + pp[2048 + q * 512 + j];
            float gf = gmv[1] + pp[q * 512 + 128 + j]  + pp[2048 + q * 512 + 128 + j];
            float gg = gmv[2] + pp[q * 512 + 256 + j]  + pp[2048 + q * 512 + 256 + j];
            float go = gmv[3] + pp[q * 512 + 384 + j]  + pp[2048 + q * 512 + 384 + j];
            float cn = sigmoidf_(gf) * creg + sigmoidf_(gi) * tanhf(gg);
            creg = cn;
            float ho = sigmoidf_(go) * tanhf(cn);
            float dec = (t == T_STEPS - 1) ? 1.0f : ng;
            sh[q * 128 + j] = ho * dec;
        }

        cx = nx; cm = nm; cb = nb; cden = nden;
    }

    __syncthreads();

    // --- custom_loss ---
    pp[q * 128 + j] = lsum;
    __syncthreads();
    if (tid < 4) {
        float s = 0.0f;
        for (int k = 0; k < 128; k++) s += pp[tid * 128 + k];
        out_loss[b0 + tid] = s * (1.0f / T_STEPS);
    }
    __syncthreads();

    // --- predictions = relu(h @ Wd + bd) @ Wo + bo ---
    float pa = bd[j];
    for (int k = 0; k < 128; k++)
        pa = fmaf(sh[q * 128 + k], Wd[k * DD + j], pa);
    pp[q * 128 + j] = fmaxf(pa, 0.0f) * Wo[j];
    __syncthreads();
    if (tid < 4) {
        float s = 0.0f;
        for (int k = 0; k < 128; k++) s += pp[tid * 128 + k];
        out_pred[b0 + tid] = s + bo[0];
    }
}

// ---------------------------------------------------------------------------
extern "C" void kernel_launch(void* const* d_in, const int* in_sizes, int n_in,
                              void* d_out, int out_size)
{
    const float* values = (const float*)d_in[0];
    const float* masks  = (const float*)d_in[1];
    const float* deltas = (const float*)d_in[2];
    const float* Wth    = (const float*)d_in[3];
    const float* bth    = (const float*)d_in[4];
    const float* Wtx    = (const float*)d_in[5];
    const float* btx    = (const float*)d_in[6];
    const float* Whr    = (const float*)d_in[7];
    const float* bhr    = (const float*)d_in[8];
    const float* Wfr    = (const float*)d_in[9];
    const float* bfr    = (const float*)d_in[10];
    const float* Wwc    = (const float*)d_in[11];
    const float* bwc    = (const float*)d_in[12];
    const float* Wk     = (const float*)d_in[13];
    const float* Wr     = (const float*)d_in[14];
    const float* bl     = (const float*)d_in[15];
    const float* Wd     = (const float*)d_in[16];
    const float* bd     = (const float*)d_in[17];
    const float* Wo     = (const float*)d_in[18];
    const float* bo     = (const float*)d_in[19];

    float *pGh, *pGx, *pBeta, *pGm, *pDen, *pWthT, *pWtxT, *pWhrQ, *pWfrQ;
    __half* pWg16;
    cudaGetSymbolAddress((void**)&pGh,   g_Gh);
    cudaGetSymbolAddress((void**)&pGx,   g_Gx);
    cudaGetSymbolAddress((void**)&pBeta, g_Beta);
    cudaGetSymbolAddress((void**)&pGm,   g_Gm);
    cudaGetSymbolAddress((void**)&pDen,  g_den);
    cudaGetSymbolAddress((void**)&pWthT, g_WthT);
    cudaGetSymbolAddress((void**)&pWtxT, g_WtxT);
    cudaGetSymbolAddress((void**)&pWhrQ, g_WhrQ);
    cudaGetSymbolAddress((void**)&pWfrQ, g_WfrQ);
    cudaGetSymbolAddress((void**)&pWg16, g_Wg16);

    // Launch 0: prep (incl. denom + fp16 weight conversion)
    prep_weights<<<512, 256>>>(Wth, Wtx, Whr, Wfr, Wk, Wr, masks,
                               pWthT, pWtxT, pWhrQ, pWfrQ, pWg16, pDen);

    // Launch 1: merged GEMM (Gh, Gx, Gm)
    dim3 gm(1024, 12);
    gemm_merged<<<gm, 256>>>(deltas, masks, pWthT, bth, pWtxT, btx,
                             Wk + 128 * 512, bl, pGh, pGx, pGm);

    // Launch 2: Beta (consumes Gx)
    dim3 gb(1024, 2);
    gemm_beta<<<gb, 256>>>(pGx, masks, Wwc, bwc, pBeta);

    // Launch 3: sequential recurrence
    float* out = (float*)d_out;
    const size_t SMEM = (size_t)38656 * sizeof(float);   // 154,624 B
    cudaFuncSetAttribute(seq_kernel, cudaFuncAttributeMaxDynamicSharedMemorySize, (int)SMEM);
    seq_kernel<<<128, 512, SMEM>>>(values, masks, pWhrQ, bhr, bfr, pWfrQ,
                                   pGh, pBeta, pGm, pDen,
                                   Wd, bd, Wo, bo, pWg16,
                                   out,                     // predictions [512]
                                   out + 512,               // imputations [512*128*128]
                                   out + 512 + 8388608);    // custom_loss [512]
}